// round 8
// baseline (speedup 1.0000x reference)
#include <cuda_runtime.h>
#include <cuda_bf16.h>
#include <cstdint>

#define BB   128
#define SS   64
#define DD   32
#define ND   200000
#define NNZT 4000000
#define SDS  258   // bf16 sd stride: 129 f32-banks -> conflict-free column reads
#define NW   6250  // ND/32 exactly
#define WPR  6256  // padded words/row

// ---------------- device scratch ----------------
__device__ float    g_s_set[BB * DD];
__device__ float    g_common[BB * DD];
__device__ float    g_row_a[ND];
__device__ float    g_colsum[ND];
__device__ float    g_diffacc[BB * DD];
__device__ float    g_sdiff[BB];
__device__ unsigned g_bits[BB * WPR];
__device__ double   g_bce;
__device__ double   g_neg1;

// ---------------- packed f32x2 helpers ----------------
__device__ __forceinline__ unsigned long long pk2(float lo, float hi) {
    unsigned long long r;
    asm("mov.b64 %0, {%1, %2};" : "=l"(r) : "f"(lo), "f"(hi));
    return r;
}
__device__ __forceinline__ void ffma2(unsigned long long& acc,
                                      unsigned long long a, unsigned long long b) {
    asm("fma.rn.f32x2 %0, %1, %2, %0;" : "+l"(acc) : "l"(a), "l"(b));
}
__device__ __forceinline__ float hsum2(unsigned long long a, unsigned long long b) {
    unsigned long long s;
    asm("add.rn.f32x2 %0, %1, %2;" : "=l"(s) : "l"(a), "l"(b));
    float x, y;
    asm("mov.b64 {%0, %1}, %2;" : "=f"(x), "=f"(y) : "l"(s));
    return x + y;
}
__device__ __forceinline__ float fast_tanh(float x) {
    float r;
    asm("tanh.approx.f32 %0, %1;" : "=f"(r) : "f"(x));
    return r;
}

// ---------------- kernel 0 ----------------
__global__ void k_init() {
    int i = blockIdx.x * blockDim.x + threadIdx.x;
    int stride = gridDim.x * blockDim.x;
    for (int j = i; j < ND; j += stride) g_row_a[j] = 0.f;
    for (int j = i; j < BB * WPR; j += stride) g_bits[j] = 0u;
    if (i < BB * DD) g_diffacc[i] = 0.f;
    if (i < BB) g_sdiff[i] = 0.f;
    if (i == 0) { g_bce = 0.0; g_neg1 = 0.0; }
}

// ---------------- kernel 1: row_a segment_sum ----------------
__global__ void k_hist(const int* __restrict__ idx, const float* __restrict__ val) {
    int i = blockIdx.x * blockDim.x + threadIdx.x;
    int stride = gridDim.x * blockDim.x;
    for (int j = i; j < NNZT; j += stride)
        atomicAdd(&g_row_a[idx[j]], val[j]);
}

// ---------------- kernel 1b: pack binary drugs to bits ----------------
__global__ void k_pack(const float* __restrict__ drugs) {
    int lane = threadIdx.x & 31;
    int gw = blockIdx.x * (blockDim.x >> 5) + (threadIdx.x >> 5);
    int wstride = gridDim.x * (blockDim.x >> 5);
    int total = BB * NW;
    for (; gw < total; gw += wstride) {
        int row = gw / NW, word = gw - row * NW;
        float v = drugs[(size_t)row * ND + word * 32 + lane];
        unsigned m = __ballot_sync(0xffffffffu, v != 0.f);
        if (lane == 0) g_bits[row * WPR + word] = m;
    }
}

// ---------------- kernel 2: s_set + common_embed ----------------
__global__ void k_attn(const int* __restrict__ syms, const int* __restrict__ simidx,
                       const float* __restrict__ sym_emb,
                       const float* __restrict__ w, const float* __restrict__ bvec) {
    int b = blockIdx.x;
    int s = threadIdx.x;
    __shared__ float sw[DD];
    __shared__ float sl[SS];
    __shared__ float sred[SS][DD];
    __shared__ float smax, ssum;
    if (s < DD) sw[s] = w[s];
    float b0 = bvec[0];
    __syncthreads();

    int sym = syms[b * SS + s];
    float x[DD];
    {
        const float4* rp = (const float4*)(sym_emb + (size_t)sym * DD);
#pragma unroll
        for (int q = 0; q < DD / 4; q++) {
            float4 v = rp[q];
            x[4 * q + 0] = v.x; x[4 * q + 1] = v.y; x[4 * q + 2] = v.z; x[4 * q + 3] = v.w;
        }
    }
    float lg = 0.f;
#pragma unroll
    for (int k = 0; k < DD; k++) lg += x[k] * sw[k];
    lg += b0;
    sl[s] = lg;
    __syncthreads();
    if (s == 0) { float m = sl[0]; for (int j = 1; j < SS; j++) m = fmaxf(m, sl[j]); smax = m; }
    __syncthreads();
    float e = expf(lg - smax);
    sl[s] = e;
    __syncthreads();
    if (s == 0) { float t = 0.f; for (int j = 0; j < SS; j++) t += sl[j]; ssum = t; }
    __syncthreads();
    float alpha = e / ssum;
#pragma unroll
    for (int k = 0; k < DD; k++) sred[s][k] = alpha * x[k];
    __syncthreads();
    if (s < DD) {
        float acc = 0.f;
        for (int j = 0; j < SS; j++) acc += sred[j][s];
        float sq = acc * acc;
#pragma unroll
        for (int off = 16; off; off >>= 1) sq += __shfl_xor_sync(0xffffffffu, sq, off);
        float nrm = fmaxf(sqrtf(sq), 1e-12f);
        g_s_set[b * DD + s] = acc / nrm;
    }
    __syncthreads();

    int sb = simidx[b];
    int sym2 = syms[sb * SS + s];
    float vals = (float)(sym * sym2);
    float y[DD];
    {
        const float4* rp = (const float4*)(sym_emb + (size_t)s * DD);
#pragma unroll
        for (int q = 0; q < DD / 4; q++) {
            float4 v = rp[q];
            y[4 * q + 0] = vals * v.x; y[4 * q + 1] = vals * v.y;
            y[4 * q + 2] = vals * v.z; y[4 * q + 3] = vals * v.w;
        }
    }
    lg = 0.f;
#pragma unroll
    for (int k = 0; k < DD; k++) lg += y[k] * sw[k];
    lg += b0;
    sl[s] = lg;
    __syncthreads();
    if (s == 0) { float m = sl[0]; for (int j = 1; j < SS; j++) m = fmaxf(m, sl[j]); smax = m; }
    __syncthreads();
    e = expf(lg - smax);
    sl[s] = e;
    __syncthreads();
    if (s == 0) { float t = 0.f; for (int j = 0; j < SS; j++) t += sl[j]; ssum = t; }
    __syncthreads();
    alpha = e / ssum;
#pragma unroll
    for (int k = 0; k < DD; k++) sred[s][k] = alpha * y[k];
    __syncthreads();
    if (s < DD) {
        float acc = 0.f;
        for (int j = 0; j < SS; j++) acc += sred[j][s];
        g_common[b * DD + s] = acc;
    }
}

// ---------------- kernel 3a: scores, 2 columns/thread ----------------
__global__ void __launch_bounds__(256, 3) k_score(
    const float* __restrict__ drug_emb, float* __restrict__ out) {
    __shared__ float s_s[BB * DD];      // 16 KB

    int tid = threadIdx.x;
    int n0 = blockIdx.x * 512;
    int na = n0 + tid, nb2 = na + 256;
    bool va = (na < ND), vb = (nb2 < ND);

    for (int i = tid; i < BB * DD; i += 256) s_s[i] = g_s_set[i];

    unsigned long long d2a[DD / 2], d2b[DD / 2];
#pragma unroll
    for (int h = 0; h < 2; h++) {
        bool vv = h ? vb : va;
        int gn = vv ? (h ? nb2 : na) : (ND - 1);
        const float4* rp = (const float4*)(drug_emb + (size_t)(gn + 1) * DD);
        float dreg[DD];
        float sqs = 0.f;
#pragma unroll
        for (int q = 0; q < DD / 4; q++) {
            float4 v = rp[q];
            dreg[4 * q + 0] = v.x; dreg[4 * q + 1] = v.y;
            dreg[4 * q + 2] = v.z; dreg[4 * q + 3] = v.w;
            sqs += v.x * v.x + v.y * v.y + v.z * v.z + v.w * v.w;
        }
        float inv = 1.0f / fmaxf(sqrtf(sqs), 1e-12f);
        if (!vv) inv = 0.f;
        unsigned long long* dst = h ? d2b : d2a;
#pragma unroll
        for (int k = 0; k < DD / 2; k++)
            dst[k] = pk2(dreg[2 * k] * inv, dreg[2 * k + 1] * inv);
    }
    __syncthreads();

    const ulonglong2* s_s4 = (const ulonglong2*)s_s;
    float csa = 0.f, csb = 0.f;
    float* o = out + na;                // o[0] and o[256]

    for (int b = 0; b < BB; b++) {
        unsigned long long A0 = 0ull, A1 = 0ull, B0 = 0ull, B1 = 0ull;
#pragma unroll
        for (int k = 0; k < DD / 4; k++) {
            ulonglong2 sv = s_s4[b * (DD / 4) + k];
            ffma2(A0, d2a[2 * k],     sv.x);
            ffma2(A1, d2a[2 * k + 1], sv.y);
            ffma2(B0, d2b[2 * k],     sv.x);
            ffma2(B1, d2b[2 * k + 1], sv.y);
        }
        float ta = hsum2(A0, A1), tb = hsum2(B0, B1);
        float tha = fast_tanh(0.5f * ta), thb = fast_tanh(0.5f * tb);
        float sca = (ta > 0.f) ? __fmaf_rn(0.5f, tha, 0.5f) : 0.f;
        float scb = (tb > 0.f) ? __fmaf_rn(0.5f, thb, 0.5f) : 0.f;
        if (va) o[0]   = sca;
        if (vb) o[256] = scb;
        o += ND;
        csa += sca; csb += scb;
    }
    if (va) g_colsum[na]  = csa;
    if (vb) g_colsum[nb2] = csb;
}

// ---------------- kernel 3b: BCE + diff via bitmask ----------------
__global__ void __launch_bounds__(256, 3) k_bce(
    const int* __restrict__ simidx, const float* __restrict__ drug_emb) {
    extern __shared__ float smem[];
    __nv_bfloat16* sd16 = (__nv_bfloat16*)smem;            // [DD][SDS]
    float*    s_c   = smem + (DD * SDS) / 2;               // [BB*DD]
    float*    s_acc = s_c + BB * DD;                       // [BB*DD]
    unsigned* s_bit = (unsigned*)(s_acc + BB * DD);        // [BB*8]
    int*      s_sim = (int*)(s_bit + BB * 8);              // [BB]
    float*    s_sd  = (float*)(s_sim + BB);                // [BB]
    float*    s_red = s_sd + BB;                           // [256]

    int tid = threadIdx.x;
    int n0 = blockIdx.x * 256;
    int n = n0 + tid;
    bool valid = (n < ND);

    for (int i = tid; i < BB * DD; i += 256) {
        s_c[i] = g_common[i];
        s_acc[i] = 0.f;
    }
    if (tid < BB) { s_sim[tid] = simidx[tid]; s_sd[tid] = 0.f; }
    int w0 = n0 >> 5;
    for (int i = tid; i < BB * 8; i += 256)
        s_bit[i] = g_bits[(i >> 3) * WPR + w0 + (i & 7)];

    unsigned long long d2[DD / 2];
    {
        int gn = valid ? n : (ND - 1);
        const float4* rp = (const float4*)(drug_emb + (size_t)(gn + 1) * DD);
        float dreg[DD];
        float sqs = 0.f;
#pragma unroll
        for (int q = 0; q < DD / 4; q++) {
            float4 v = rp[q];
            dreg[4 * q + 0] = v.x; dreg[4 * q + 1] = v.y;
            dreg[4 * q + 2] = v.z; dreg[4 * q + 3] = v.w;
            sqs += v.x * v.x + v.y * v.y + v.z * v.z + v.w * v.w;
        }
        float inv = 1.0f / fmaxf(sqrtf(sqs), 1e-12f);
        if (!valid) inv = 0.f;
#pragma unroll
        for (int k = 0; k < DD; k++) dreg[k] *= inv;
#pragma unroll
        for (int k = 0; k < DD; k++) sd16[k * SDS + tid] = __float2bfloat16(dreg[k]);
#pragma unroll
        for (int k = 0; k < DD / 2; k++) d2[k] = pk2(dreg[2 * k], dreg[2 * k + 1]);
    }
    __syncthreads();

    int warp = tid >> 5, lane = tid & 31;
    float bce = 0.f;
    const ulonglong2* s_c4 = (const ulonglong2*)s_c;

    for (int it = 0; it < BB; it++) {
        int b = (it + (warp << 4)) & (BB - 1);   // warp owns b (stagger)
        unsigned ow = s_bit[b * 8 + warp];
        unsigned sw = s_bit[s_sim[b] * 8 + warp];

        unsigned long long c0 = 0ull, c1 = 0ull;
#pragma unroll
        for (int k = 0; k < DD / 4; k++) {
            ulonglong2 cv = s_c4[b * (DD / 4) + k];
            ffma2(c0, d2[2 * k],     cv.x);
            ffma2(c1, d2[2 * k + 1], cv.y);
        }
        float z = hsum2(c0, c1);

        float cd = (float)((ow & sw) >> lane & 1u);
        float sp = fmaxf(z, 0.f) + __logf(1.f + __expf(-fabsf(z)));
        bce += valid ? (sp - z * cd) : 0.f;

        unsigned m = ow ^ sw;                    // exact diff ballot
        if (m) {
            if (lane == 0) s_sd[b] += (float)__popc(m);
            const __nv_bfloat16* col = sd16 + lane * SDS + (warp << 5);
            float sum = 0.f;
            unsigned mm = m;
            do {
                int j = __ffs(mm) - 1; mm &= (mm - 1);
                sum += __bfloat162float(col[j]);
            } while (mm);
            s_acc[b * DD + lane] += sum;
        }
        if ((it & 7) == 7) __syncthreads();
    }

    s_red[tid] = bce;
    __syncthreads();
    for (int st = 128; st; st >>= 1) {
        if (tid < st) s_red[tid] += s_red[tid + st];
        __syncthreads();
    }
    if (tid == 0) atomicAdd(&g_bce, (double)s_red[0]);
    __syncthreads();

    for (int i = tid; i < BB * DD; i += 256) atomicAdd(&g_diffacc[i], s_acc[i]);
    if (tid < BB) atomicAdd(&g_sdiff[tid], s_sd[tid]);
}

// ---------------- kernel 3c: neg1 = dot(colsum, row_a) ----------------
__global__ void k_tail() {
    __shared__ float sred[256];
    int tid = threadIdx.x;
    int i = blockIdx.x * blockDim.x + tid;
    int stride = gridDim.x * blockDim.x;
    float acc = 0.f;
    for (int j = i; j < ND; j += stride) acc += g_colsum[j] * g_row_a[j];
    sred[tid] = acc;
    __syncthreads();
    for (int st = 128; st; st >>= 1) {
        if (tid < st) sred[tid] += sred[tid + st];
        __syncthreads();
    }
    if (tid == 0) atomicAdd(&g_neg1, (double)sred[0]);
}

// ---------------- kernel 4: scalars ----------------
__global__ void k_final(float* __restrict__ out) {
    int b = threadIdx.x;
    __shared__ float sred[BB];
    float acc = 0.f;
    float sdv = g_sdiff[b] + 1e-6f;
#pragma unroll
    for (int k = 0; k < DD; k++) {
        float de = g_diffacc[b * DD + k] / sdv;
        float x = g_common[b * DD + k] * de;
        acc += 1.0f / (1.0f + __expf(-x));
    }
    sred[b] = acc;
    __syncthreads();
    for (int st = 64; st; st >>= 1) {
        if (b < st) sred[b] += sred[b + st];
        __syncthreads();
    }
    if (b == 0) {
        out[(size_t)BB * ND]     = (float)(g_bce / (double)((double)BB * (double)ND));
        out[(size_t)BB * ND + 1] = (float)(1e-6 * g_neg1 + 1e-4 * (double)sred[0]);
    }
}

// ---------------- launcher (stream overlap, capture-safe fork/join) --------
extern "C" void kernel_launch(void* const* d_in, const int* in_sizes, int n_in,
                              void* d_out, int out_size) {
    const int*   syms     = (const int*)d_in[0];
    const float* drugs    = (const float*)d_in[1];
    const int*   simidx   = (const int*)d_in[2];
    const int*   ddi_idx  = (const int*)d_in[3];
    const float* ddi_val  = (const float*)d_in[4];
    const float* sym_emb  = (const float*)d_in[5];
    const float* drug_emb = (const float*)d_in[6];
    const float* attn_w   = (const float*)d_in[7];
    const float* attn_b   = (const float*)d_in[8];
    float* out = (float*)d_out;

    static cudaStream_t s2 = nullptr;
    static cudaEvent_t ev0 = nullptr, ev1 = nullptr;
    static bool attr_set = false;
    const int smem_bce = (DD * SDS) * 2 + (2 * BB * DD) * 4 + BB * 8 * 4
                       + BB * 4 + BB * 4 + 256 * 4;
    if (!attr_set) {
        cudaFuncSetAttribute(k_bce, cudaFuncAttributeMaxDynamicSharedMemorySize, smem_bce);
        cudaStreamCreateWithFlags(&s2, cudaStreamNonBlocking);
        cudaEventCreateWithFlags(&ev0, cudaEventDisableTiming);
        cudaEventCreateWithFlags(&ev1, cudaEventDisableTiming);
        attr_set = true;
    }

    // main stream: init -> attn -> score -> [join] -> bce -> tail -> final
    // side stream: hist + pack (DRAM/L2-bound), overlapped with L1-bound work
    k_init<<<512, 256>>>();
    cudaEventRecord(ev0, 0);
    cudaStreamWaitEvent(s2, ev0, 0);
    k_hist<<<2048, 256, 0, s2>>>(ddi_idx, ddi_val);
    k_pack<<<1024, 256, 0, s2>>>(drugs);
    cudaEventRecord(ev1, s2);

    k_attn<<<BB, SS>>>(syms, simidx, sym_emb, attn_w, attn_b);
    k_score<<<(ND + 511) / 512, 256>>>(drug_emb, out);

    cudaStreamWaitEvent(0, ev1, 0);            // bits + row_a ready
    k_bce<<<(ND + 255) / 256, 256, smem_bce>>>(simidx, drug_emb);
    k_tail<<<256, 256>>>();
    k_final<<<1, BB>>>(out);
}

// round 9
// speedup vs baseline: 1.0715x; 1.0715x over previous
#include <cuda_runtime.h>
#include <cuda_bf16.h>
#include <cstdint>

#define BB   128
#define SS   64
#define DD   32
#define ND   200000
#define NNZT 4000000
#define TN   512            // columns per block (1 per thread)
#define SDS2 516            // bf16 tile stride (columns padded)

// ---------------- device scratch ----------------
__device__ float  g_s_set[BB * DD];
__device__ float  g_common[BB * DD];
__device__ float  g_row_a[ND];
__device__ float  g_diffacc[BB * DD];
__device__ float  g_sdiff[BB];
__device__ double g_bce;
__device__ double g_neg1;

// ---------------- packed f32x2 helpers ----------------
__device__ __forceinline__ unsigned long long pk2(float lo, float hi) {
    unsigned long long r;
    asm("mov.b64 %0, {%1, %2};" : "=l"(r) : "f"(lo), "f"(hi));
    return r;
}
__device__ __forceinline__ void ffma2(unsigned long long& acc,
                                      unsigned long long a, unsigned long long b) {
    asm("fma.rn.f32x2 %0, %1, %2, %0;" : "+l"(acc) : "l"(a), "l"(b));
}
__device__ __forceinline__ float hsum2(unsigned long long a, unsigned long long b) {
    unsigned long long s;
    asm("add.rn.f32x2 %0, %1, %2;" : "=l"(s) : "l"(a), "l"(b));
    float x, y;
    asm("mov.b64 {%0, %1}, %2;" : "=f"(x), "=f"(y) : "l"(s));
    return x + y;
}
__device__ __forceinline__ float fast_tanh(float x) {
    float r;
    asm("tanh.approx.f32 %0, %1;" : "=f"(r) : "f"(x));
    return r;
}

// ---------------- kernel 0 ----------------
__global__ void k_init() {
    int i = blockIdx.x * blockDim.x + threadIdx.x;
    int stride = gridDim.x * blockDim.x;
    for (int j = i; j < ND; j += stride) g_row_a[j] = 0.f;
    if (i < BB * DD) g_diffacc[i] = 0.f;
    if (i < BB) g_sdiff[i] = 0.f;
    if (i == 0) { g_bce = 0.0; g_neg1 = 0.0; }
}

// ---------------- kernel 1: row_a segment_sum ----------------
__global__ void k_hist(const int* __restrict__ idx, const float* __restrict__ val) {
    int i = blockIdx.x * blockDim.x + threadIdx.x;
    int stride = gridDim.x * blockDim.x;
    for (int j = i; j < NNZT; j += stride)
        atomicAdd(&g_row_a[idx[j]], val[j]);
}

// ---------------- kernel 2: s_set + common_embed ----------------
__global__ void k_attn(const int* __restrict__ syms, const int* __restrict__ simidx,
                       const float* __restrict__ sym_emb,
                       const float* __restrict__ w, const float* __restrict__ bvec) {
    int b = blockIdx.x;
    int s = threadIdx.x;
    __shared__ float sw[DD];
    __shared__ float sl[SS];
    __shared__ float sred[SS][DD];
    __shared__ float smax, ssum;
    if (s < DD) sw[s] = w[s];
    float b0 = bvec[0];
    __syncthreads();

    int sym = syms[b * SS + s];
    float x[DD];
    {
        const float4* rp = (const float4*)(sym_emb + (size_t)sym * DD);
#pragma unroll
        for (int q = 0; q < DD / 4; q++) {
            float4 v = rp[q];
            x[4 * q + 0] = v.x; x[4 * q + 1] = v.y; x[4 * q + 2] = v.z; x[4 * q + 3] = v.w;
        }
    }
    float lg = 0.f;
#pragma unroll
    for (int k = 0; k < DD; k++) lg += x[k] * sw[k];
    lg += b0;
    sl[s] = lg;
    __syncthreads();
    if (s == 0) { float m = sl[0]; for (int j = 1; j < SS; j++) m = fmaxf(m, sl[j]); smax = m; }
    __syncthreads();
    float e = expf(lg - smax);
    sl[s] = e;
    __syncthreads();
    if (s == 0) { float t = 0.f; for (int j = 0; j < SS; j++) t += sl[j]; ssum = t; }
    __syncthreads();
    float alpha = e / ssum;
#pragma unroll
    for (int k = 0; k < DD; k++) sred[s][k] = alpha * x[k];
    __syncthreads();
    if (s < DD) {
        float acc = 0.f;
        for (int j = 0; j < SS; j++) acc += sred[j][s];
        float sq = acc * acc;
#pragma unroll
        for (int off = 16; off; off >>= 1) sq += __shfl_xor_sync(0xffffffffu, sq, off);
        float nrm = fmaxf(sqrtf(sq), 1e-12f);
        g_s_set[b * DD + s] = acc / nrm;
    }
    __syncthreads();

    int sb = simidx[b];
    int sym2 = syms[sb * SS + s];
    float vals = (float)(sym * sym2);
    float y[DD];
    {
        const float4* rp = (const float4*)(sym_emb + (size_t)s * DD);
#pragma unroll
        for (int q = 0; q < DD / 4; q++) {
            float4 v = rp[q];
            y[4 * q + 0] = vals * v.x; y[4 * q + 1] = vals * v.y;
            y[4 * q + 2] = vals * v.z; y[4 * q + 3] = vals * v.w;
        }
    }
    lg = 0.f;
#pragma unroll
    for (int k = 0; k < DD; k++) lg += y[k] * sw[k];
    lg += b0;
    sl[s] = lg;
    __syncthreads();
    if (s == 0) { float m = sl[0]; for (int j = 1; j < SS; j++) m = fmaxf(m, sl[j]); smax = m; }
    __syncthreads();
    e = expf(lg - smax);
    sl[s] = e;
    __syncthreads();
    if (s == 0) { float t = 0.f; for (int j = 0; j < SS; j++) t += sl[j]; ssum = t; }
    __syncthreads();
    alpha = e / ssum;
#pragma unroll
    for (int k = 0; k < DD; k++) sred[s][k] = alpha * y[k];
    __syncthreads();
    if (s < DD) {
        float acc = 0.f;
        for (int j = 0; j < SS; j++) acc += sred[j][s];
        g_common[b * DD + s] = acc;
    }
}

// ---------------- kernel 3: fused mainloop, 512-thread CTA, 2 CTAs/SM ------
__global__ void __launch_bounds__(512, 2) k_main(
    const float* __restrict__ drugs, const int* __restrict__ simidx,
    const float* __restrict__ drug_emb, float* __restrict__ out) {
    extern __shared__ float smem[];
    __nv_bfloat16* sd16 = (__nv_bfloat16*)smem;            // [DD][SDS2] 33 KB
    float* s_s   = smem + (DD * SDS2) / 2;                 // [BB*DD] 16 KB
    float* s_c   = s_s + BB * DD;                          // [BB*DD] 16 KB
    float* s_acc = s_c + BB * DD;                          // [BB*DD] 16 KB
    unsigned long long* s_soff = (unsigned long long*)(s_acc + BB * DD);  // [BB] 1 KB
    float* s_sd  = (float*)(s_soff + BB);                  // [BB]
    float* s_red = s_sd + BB;                              // [512]

    int tid = threadIdx.x;
    int n = blockIdx.x * TN + tid;
    bool valid = (n < ND);

    for (int i = tid; i < BB * DD; i += TN) {
        s_s[i] = g_s_set[i];
        s_c[i] = g_common[i];
        s_acc[i] = 0.f;
    }
    if (tid < BB) {
        s_soff[tid] = (unsigned long long)simidx[tid] * ND;
        s_sd[tid] = 0.f;
    }

    // per-thread d row, normalize into packed regs + bf16 tile
    unsigned long long d2[DD / 2];
    {
        int gn = valid ? n : (ND - 1);
        const float4* rp = (const float4*)(drug_emb + (size_t)(gn + 1) * DD);
        float dreg[DD];
        float sqs = 0.f;
#pragma unroll
        for (int q = 0; q < DD / 4; q++) {
            float4 v = rp[q];
            dreg[4 * q + 0] = v.x; dreg[4 * q + 1] = v.y;
            dreg[4 * q + 2] = v.z; dreg[4 * q + 3] = v.w;
            sqs += v.x * v.x + v.y * v.y + v.z * v.z + v.w * v.w;
        }
        float inv = 1.0f / fmaxf(sqrtf(sqs), 1e-12f);
        if (!valid) inv = 0.f;
#pragma unroll
        for (int k = 0; k < DD; k++) dreg[k] *= inv;
#pragma unroll
        for (int k = 0; k < DD; k++) sd16[k * SDS2 + tid] = __float2bfloat16(dreg[k]);
#pragma unroll
        for (int k = 0; k < DD / 2; k++) d2[k] = pk2(dreg[2 * k], dreg[2 * k + 1]);
    }
    __syncthreads();

    int warp = tid >> 5, lane = tid & 31;
    float colsum = 0.f, bce = 0.f;
    const ulonglong2* s_s4 = (const ulonglong2*)s_s;
    const ulonglong2* s_c4 = (const ulonglong2*)s_c;
    const float* dA = drugs + (valid ? n : 0);
    float* oA = out + (valid ? n : 0);

    // stagger 8 per warp (16 warps x 8 = 128); incremental row offset w/ wrap
    int b_cur = (warp << 3) & (BB - 1);
    size_t off = (size_t)b_cur * ND;
    float db = valid ? dA[off] : 0.f;
    float ds = valid ? dA[s_soff[b_cur]] : 0.f;

    for (int it = 0; it < BB; it++) {
        int b = b_cur;
        size_t off_b = off;
        // advance + prefetch next
        int b_nxt = (b + 1) & (BB - 1);
        size_t off_n = (b == BB - 1) ? 0 : off + ND;
        float db_n = 0.f, ds_n = 0.f;
        if (it + 1 < BB && valid) {
            db_n = dA[off_n];
            ds_n = dA[s_soff[b_nxt]];
        }

        // dual dot via broadcast LDS.128
        unsigned long long a0 = 0ull, a1 = 0ull, c0 = 0ull, c1 = 0ull;
#pragma unroll
        for (int k = 0; k < DD / 4; k++) {
            ulonglong2 sv = s_s4[b * (DD / 4) + k];
            ulonglong2 cv = s_c4[b * (DD / 4) + k];
            unsigned long long dk = d2[2 * k], dk1 = d2[2 * k + 1];
            ffma2(a0, dk,  sv.x);
            ffma2(c0, dk,  cv.x);
            ffma2(a1, dk1, sv.y);
            ffma2(c1, dk1, cv.y);
        }
        float t = hsum2(a0, a1);
        float z = hsum2(c0, c1);

        float th = fast_tanh(0.5f * t);
        float score = (t > 0.f) ? __fmaf_rn(0.5f, th, 0.5f) : 0.f;
        if (valid) oA[off_b] = score;
        colsum += score;

        float cd = db * ds;
        float az = fabsf(z);
        float soft = __logf(1.f + __expf(-az));
        float term = fmaxf(z, 0.f) - z * cd + soft;
        bce += valid ? term : 0.f;

        // diff branch: ballot-compacted bf16 adds (warp owns b via stagger)
        unsigned m = __ballot_sync(0xffffffffu, db != ds);
        if (m) {
            if (lane == 0) s_sd[b] += (float)__popc(m);
            const __nv_bfloat16* col = sd16 + lane * SDS2 + (warp << 5);
            float sum = 0.f;
            unsigned mm = m;
            do {
                int j = __ffs(mm) - 1; mm &= (mm - 1);
                sum += __bfloat162float(col[j]);
            } while (mm);
            s_acc[b * DD + lane] += sum;
        }

        db = db_n; ds = ds_n; b_cur = b_nxt; off = off_n;
        if ((it & 3) == 3) __syncthreads();   // skew <= 3 < stagger 8
    }

    // epilogue reductions
    float v = valid ? colsum * g_row_a[n] : 0.f;
    s_red[tid] = bce;
    __syncthreads();
    for (int st = 256; st; st >>= 1) {
        if (tid < st) s_red[tid] += s_red[tid + st];
        __syncthreads();
    }
    if (tid == 0) atomicAdd(&g_bce, (double)s_red[0]);
    __syncthreads();

    s_red[tid] = v;
    __syncthreads();
    for (int st = 256; st; st >>= 1) {
        if (tid < st) s_red[tid] += s_red[tid + st];
        __syncthreads();
    }
    if (tid == 0) atomicAdd(&g_neg1, (double)s_red[0]);
    __syncthreads();

    for (int i = tid; i < BB * DD; i += TN) atomicAdd(&g_diffacc[i], s_acc[i]);
    if (tid < BB) atomicAdd(&g_sdiff[tid], s_sd[tid]);
}

// ---------------- kernel 4: scalars ----------------
__global__ void k_final(float* __restrict__ out) {
    int b = threadIdx.x;
    __shared__ float sred[BB];
    float acc = 0.f;
    float sdv = g_sdiff[b] + 1e-6f;
#pragma unroll
    for (int k = 0; k < DD; k++) {
        float de = g_diffacc[b * DD + k] / sdv;
        float x = g_common[b * DD + k] * de;
        acc += 1.0f / (1.0f + __expf(-x));
    }
    sred[b] = acc;
    __syncthreads();
    for (int st = 64; st; st >>= 1) {
        if (b < st) sred[b] += sred[b + st];
        __syncthreads();
    }
    if (b == 0) {
        out[(size_t)BB * ND]     = (float)(g_bce / (double)((double)BB * (double)ND));
        out[(size_t)BB * ND + 1] = (float)(1e-6 * g_neg1 + 1e-4 * (double)sred[0]);
    }
}

// ---------------- launcher ----------------
extern "C" void kernel_launch(void* const* d_in, const int* in_sizes, int n_in,
                              void* d_out, int out_size) {
    const int*   syms     = (const int*)d_in[0];
    const float* drugs    = (const float*)d_in[1];
    const int*   simidx   = (const int*)d_in[2];
    const int*   ddi_idx  = (const int*)d_in[3];
    const float* ddi_val  = (const float*)d_in[4];
    const float* sym_emb  = (const float*)d_in[5];
    const float* drug_emb = (const float*)d_in[6];
    const float* attn_w   = (const float*)d_in[7];
    const float* attn_b   = (const float*)d_in[8];
    float* out = (float*)d_out;

    static bool attr_set = false;
    const int smem_bytes = (DD * SDS2) * 2 + (3 * BB * DD) * 4 + BB * 8
                         + BB * 4 + 512 * 4;
    if (!attr_set) {
        cudaFuncSetAttribute(k_main, cudaFuncAttributeMaxDynamicSharedMemorySize, smem_bytes);
        attr_set = true;
    }

    k_init<<<256, 256>>>();
    k_hist<<<2048, 256>>>(ddi_idx, ddi_val);   // row_a ready before k_main epilogue
    k_attn<<<BB, SS>>>(syms, simidx, sym_emb, attn_w, attn_b);
    int nb = (ND + TN - 1) / TN;               // 391 blocks
    k_main<<<nb, 512, smem_bytes>>>(drugs, simidx, drug_emb, out);
    k_final<<<1, BB>>>(out);
}